// round 4
// baseline (speedup 1.0000x reference)
#include <cuda_runtime.h>
#include <cstdint>
#include <cstddef>

// DPQNetwork: r[b,c,k] = sum_d X[b,c,d]*Yc[c,k,d]; BN over (B,K) per channel;
// outputs: codes=argmax_k (f32), mse=max_k normalized, centroids pass-through.
// BN is a monotone-increasing per-channel affine (gamma=1) => argmax/max on RAW
// r, affine applied afterward; r (537 MB) never touches HBM.
//
// R4 vs R3 (fma=53%, L1=69%, issue=41%):
//  - X staged in smem PRE-DUPLICATED as u64 (x,x): dup-MOVs (16/d-pair, each an
//    ALU->FMA dep chain) removed; X operand for 2 d's = one LDS.128.
//  - Y loads widened to LDS.128 (2 k-pairs per load).
//  - inner loop: 64 FFMA2 + 12 LDS.128 per d-pair, zero MOVs.

#define NB 8192
#define NC 64
#define NK 256
#define ND 64
#define GRIDX 128            // NB / 64 rows per block
#define YSTRIDE 130          // u64 per d-row of Ys2 (128 k-pairs + pad)
#define XDS 66               // u64 per b-row of Xd (64 dup'd d + pad)

__device__ float g_psum[NC * GRIDX];
__device__ float g_psumsq[NC * GRIDX];
__device__ float g_affA[NC];
__device__ float g_affB[NC];

__device__ __forceinline__ unsigned long long f32x2_dup(float x) {
    unsigned long long r;
    asm("mov.b64 %0, {%1, %1};" : "=l"(r) : "f"(x));
    return r;
}
__device__ __forceinline__ unsigned long long f32x2_pack(float lo, float hi) {
    unsigned long long r;
    asm("mov.b64 %0, {%1, %2};" : "=l"(r) : "f"(lo), "f"(hi));
    return r;
}
__device__ __forceinline__ void f32x2_fma(unsigned long long& acc,
                                          unsigned long long a,
                                          unsigned long long b) {
    asm("fma.rn.f32x2 %0, %1, %2, %0;" : "+l"(acc) : "l"(a), "l"(b));
}
__device__ __forceinline__ void f32x2_unpack(unsigned long long v,
                                             float& lo, float& hi) {
    asm("mov.b64 {%0, %1}, %2;" : "=f"(lo), "=f"(hi) : "l"(v));
}

__global__ __launch_bounds__(256, 2) void dpq_main(
    const float* __restrict__ X,    // (B, C, D)
    const float* __restrict__ Yc,   // (C, K, D)
    float* __restrict__ out)        // [0,B*C): codes  [B*C,2B*C): raw max
{
    extern __shared__ __align__(16) char smraw[];
    unsigned long long* Ys2 = (unsigned long long*)smraw;    // 64*YSTRIDE u64
    unsigned long long* Xd  = Ys2 + 64 * YSTRIDE;            // 64*XDS u64 (dup)
    float* smax = (float*)(Xd + 64 * XDS);                   // 8 warps * 64
    int*   sidx = (int*)(smax + 512);                        // 8 * 64
    float* wsum = (float*)(sidx + 512);                      // 8
    float* wsq  = wsum + 8;                                  // 8

    const int c    = blockIdx.y;
    const int b0   = blockIdx.x * 64;
    const int tid  = threadIdx.x;
    const int lane = tid & 31;
    const int warp = tid >> 5;
    const int bsub = lane & 7;               // lane's base b-row (rows bsub+8i)
    const int kq   = lane >> 3;              // 4 k-quarters per warp
    const int kp0  = (warp * 4 + kq) * 4;    // first k-PAIR index (4 pairs=8 k)

    // ---- stage X rows [b0,b0+64) of channel c, duplicated per element ----
#pragma unroll
    for (int s = 0; s < 4; s++) {
        int idx = s * 256 + tid;
        int row = idx >> 4, q = idx & 15;
        float4 v = ((const float4*)(X + ((size_t)(b0 + row) * NC + c) * ND))[q];
        unsigned long long* dst = Xd + row * XDS + q * 4;
        dst[0] = f32x2_dup(v.x);
        dst[1] = f32x2_dup(v.y);
        dst[2] = f32x2_dup(v.z);
        dst[3] = f32x2_dup(v.w);
    }
    // ---- stage Y[c] transposed into k-pair-packed u64: Ys2[d][kp] ----
    const float* Yg = Yc + (size_t)c * NK * ND;
#pragma unroll
    for (int t = 0; t < 8; t++) {
        int idx = t * 256 + tid;             // 0..2047
        int kp = idx & 127, dc = idx >> 7;   // dc: 16 chunks of 4 d
        float4 a = *(const float4*)(Yg + (2 * kp)     * ND + dc * 4);
        float4 b = *(const float4*)(Yg + (2 * kp + 1) * ND + dc * 4);
        Ys2[(dc * 4 + 0) * YSTRIDE + kp] = f32x2_pack(a.x, b.x);
        Ys2[(dc * 4 + 1) * YSTRIDE + kp] = f32x2_pack(a.y, b.y);
        Ys2[(dc * 4 + 2) * YSTRIDE + kp] = f32x2_pack(a.z, b.z);
        Ys2[(dc * 4 + 3) * YSTRIDE + kp] = f32x2_pack(a.w, b.w);
    }
    __syncthreads();

    // ---- 8 b-rows x 8 k-cols per thread; acc as 4 packed f32x2 per row ----
    unsigned long long acc[8][4];
#pragma unroll
    for (int i = 0; i < 8; i++)
#pragma unroll
        for (int j = 0; j < 4; j++) acc[i][j] = 0ull;

    const unsigned long long* xbase = Xd + bsub * XDS;   // rows bsub + 8i
    const unsigned long long* ybase = Ys2 + kp0;

#pragma unroll 4
    for (int d = 0; d < ND; d += 2) {
        // X: one LDS.128 per row covers (dup d, dup d+1)
        ulonglong2 xv[8];
#pragma unroll
        for (int i = 0; i < 8; i++)
            xv[i] = *(const ulonglong2*)(xbase + i * 8 * XDS + d);
        // Y: 2 LDS.128 per d (4 k-pairs)
        ulonglong2 ya0 = *(const ulonglong2*)(ybase + (d)     * YSTRIDE);
        ulonglong2 ya1 = *(const ulonglong2*)(ybase + (d)     * YSTRIDE + 2);
        ulonglong2 yb0 = *(const ulonglong2*)(ybase + (d + 1) * YSTRIDE);
        ulonglong2 yb1 = *(const ulonglong2*)(ybase + (d + 1) * YSTRIDE + 2);
#pragma unroll
        for (int i = 0; i < 8; i++) {
            f32x2_fma(acc[i][0], xv[i].x, ya0.x);
            f32x2_fma(acc[i][1], xv[i].x, ya0.y);
            f32x2_fma(acc[i][2], xv[i].x, ya1.x);
            f32x2_fma(acc[i][3], xv[i].x, ya1.y);
            f32x2_fma(acc[i][0], xv[i].y, yb0.x);
            f32x2_fma(acc[i][1], xv[i].y, yb0.y);
            f32x2_fma(acc[i][2], xv[i].y, yb1.x);
            f32x2_fma(acc[i][3], xv[i].y, yb1.y);
        }
    }

    // ---- per-row max/argmax + BN partial sums ----
    float s1 = 0.f, s2 = 0.f;
    float tmax[8]; int tidx[8];
#pragma unroll
    for (int i = 0; i < 8; i++) {
        tmax[i] = -3.4e38f; tidx[i] = 0;
#pragma unroll
        for (int j = 0; j < 4; j++) {
            float lo, hi;
            f32x2_unpack(acc[i][j], lo, hi);
            s1 += lo + hi;
            s2 = fmaf(lo, lo, s2);
            s2 = fmaf(hi, hi, s2);
            int klo = (kp0 + j) * 2;
            if (lo > tmax[i]) { tmax[i] = lo; tidx[i] = klo; }
            if (hi > tmax[i]) { tmax[i] = hi; tidx[i] = klo + 1; }
        }
    }

    // reduce max across 4 k-quarters in warp (xor 8,16 keeps bsub fixed)
#pragma unroll
    for (int i = 0; i < 8; i++) {
#pragma unroll
        for (int off = 8; off <= 16; off <<= 1) {
            float v2 = __shfl_xor_sync(0xffffffffu, tmax[i], off);
            int   i2 = __shfl_xor_sync(0xffffffffu, tidx[i], off);
            if (v2 > tmax[i] || (v2 == tmax[i] && i2 < tidx[i])) {
                tmax[i] = v2; tidx[i] = i2;
            }
        }
    }
    if (kq == 0) {
#pragma unroll
        for (int i = 0; i < 8; i++) {
            smax[warp * 64 + bsub + i * 8] = tmax[i];   // row = bsub + 8i
            sidx[warp * 64 + bsub + i * 8] = tidx[i];
        }
    }

    // warp sum for BN stats
#pragma unroll
    for (int off = 16; off > 0; off >>= 1) {
        s1 += __shfl_xor_sync(0xffffffffu, s1, off);
        s2 += __shfl_xor_sync(0xffffffffu, s2, off);
    }
    if (lane == 0) { wsum[warp] = s1; wsq[warp] = s2; }
    __syncthreads();

    // cross-warp max per row; write codes + raw max
    if (tid < 64) {
        const int row = tid;
        float m = smax[row]; int ki = sidx[row];
#pragma unroll
        for (int w = 1; w < 8; w++) {
            float v = smax[w * 64 + row]; int i2 = sidx[w * 64 + row];
            if (v > m || (v == m && i2 < ki)) { m = v; ki = i2; }
        }
        const size_t o = (size_t)(b0 + row) * NC + c;
        out[o] = (float)ki;
        out[(size_t)NB * NC + o] = m;
    }
    if (tid == 0) {
        float a = 0.f, b = 0.f;
#pragma unroll
        for (int w = 0; w < 8; w++) { a += wsum[w]; b += wsq[w]; }
        g_psum[c * GRIDX + blockIdx.x]   = a;     // single writer, deterministic
        g_psumsq[c * GRIDX + blockIdx.x] = b;
    }
}

__global__ void dpq_stats(const float* __restrict__ gamma,
                          const float* __restrict__ beta)
{
    const int c = threadIdx.x;          // 64 threads
    float s = 0.f, q = 0.f;
    for (int i = 0; i < GRIDX; i++) {
        s += g_psum[c * GRIDX + i];
        q += g_psumsq[c * GRIDX + i];
    }
    const float inv = 1.0f / ((float)NB * (float)NK);
    const float mean = s * inv;
    const float var  = q * inv - mean * mean;   // biased, matches reference
    const float a = gamma[c] * rsqrtf(var + 1e-5f);
    g_affA[c] = a;
    g_affB[c] = fmaf(-mean, a, beta[c]);
}

__global__ void dpq_final(float* __restrict__ out)
{
    const int idx = blockIdx.x * blockDim.x + threadIdx.x;
    if (idx < NB * NC) {
        const int c = idx & (NC - 1);
        float* p = out + (size_t)NB * NC + idx;
        *p = fmaf(*p, g_affA[c], g_affB[c]);
    }
}

extern "C" void kernel_launch(void* const* d_in, const int* in_sizes, int n_in,
                              void* d_out, int out_size)
{
    const float* X     = (const float*)d_in[0];  // inputs (B,C,D)
    const float* Yc    = (const float*)d_in[1];  // centroids_k (C,K,D)
    const float* gamma = (const float*)d_in[2];
    const float* beta  = (const float*)d_in[3];
    float* out = (float*)d_out;

    const size_t smem = (size_t)64 * YSTRIDE * 8     // Ys2
                      + (size_t)64 * XDS * 8         // Xd (dup'd)
                      + 512 * 4 + 512 * 4 + 16 * 4;  // reductions
    cudaFuncSetAttribute(dpq_main, cudaFuncAttributeMaxDynamicSharedMemorySize,
                         (int)smem);

    dim3 grid(GRIDX, NC);
    dpq_main<<<grid, 256, smem>>>(X, Yc, out);
    dpq_stats<<<1, NC>>>(gamma, beta);
    dpq_final<<<(NB * NC + 255) / 256, 256>>>(out);

    if (out_size >= 2 * NB * NC + NC * NK * ND) {
        cudaMemcpyAsync(out + 2 * (size_t)NB * NC, Yc,
                        (size_t)NC * NK * ND * sizeof(float),
                        cudaMemcpyDeviceToDevice, 0);
    }
}

// round 7
// speedup vs baseline: 1.1996x; 1.1996x over previous
#include <cuda_runtime.h>
#include <cstdint>
#include <cstddef>

// DPQNetwork: r[b,c,k] = sum_d X[b,c,d]*Yc[c,k,d]; BN over (B,K) per channel;
// outputs: codes=argmax_k (f32), mse=max_k normalized, centroids pass-through.
// BN is a monotone-increasing per-channel affine (gamma=1) => max/argmax on RAW
// r, affine applied after; r (537 MB) never touches HBM.
//
// R6/R7: toolchain targets sm_100 (no 'a') => no tcgen05. FFMA2 path with an
// 8x16 thread tile (vs R3's 8x8): bytes/FFMA2 drops 2.0 -> 1.5, taking the smem
// return-path (128B/cyc/SM, per-lane) from exactly-binding to 75% demand.
// Block = 128 b-rows x 256 k, 256 threads, 1 CTA/SM (~200 regs).
// (R6 bench was an infra flake — container failed pre-compile; resubmitting.)

#define NB 8192
#define NC 64
#define NK 256
#define ND 64
#define GTILES 64            // NB / 128 M-tiles
#define XPAD 68              // X smem row stride (floats)
#define YSTRIDE 130          // u64 per d-row of Ys2 (128 k-pairs + pad)

__device__ float g_psum[NC * GTILES];
__device__ float g_psumsq[NC * GTILES];
__device__ float g_affA[NC];
__device__ float g_affB[NC];

__device__ __forceinline__ unsigned long long f32x2_dup(float x) {
    unsigned long long r;
    asm("mov.b64 %0, {%1, %1};" : "=l"(r) : "f"(x));
    return r;
}
__device__ __forceinline__ unsigned long long f32x2_pack(float lo, float hi) {
    unsigned long long r;
    asm("mov.b64 %0, {%1, %2};" : "=l"(r) : "f"(lo), "f"(hi));
    return r;
}
__device__ __forceinline__ void f32x2_fma(unsigned long long& acc,
                                          unsigned long long a,
                                          unsigned long long b) {
    asm("fma.rn.f32x2 %0, %1, %2, %0;" : "+l"(acc) : "l"(a), "l"(b));
}
__device__ __forceinline__ void f32x2_unpack(unsigned long long v,
                                             float& lo, float& hi) {
    asm("mov.b64 {%0, %1}, %2;" : "=f"(lo), "=f"(hi) : "l"(v));
}

__global__ __launch_bounds__(256, 1) void dpq_main(
    const float* __restrict__ X,    // (B, C, D)
    const float* __restrict__ Yc,   // (C, K, D)
    float* __restrict__ out)        // [0,B*C): codes  [B*C,2B*C): raw max
{
    extern __shared__ __align__(16) char smraw[];
    unsigned long long* Ys2 = (unsigned long long*)smraw;    // 64*YSTRIDE u64
    float* Xs   = (float*)(Ys2 + 64 * YSTRIDE);              // 128*XPAD
    float* smax = Xs + 128 * XPAD;                           // 4 kgroups * 128
    int*   sidx = (int*)(smax + 512);                        // 4 * 128
    float* wsum = (float*)(sidx + 512);                      // 8
    float* wsq  = wsum + 8;                                  // 8

    const int c    = blockIdx.y;
    const int b0   = blockIdx.x * 128;
    const int tid  = threadIdx.x;
    const int lane = tid & 31;
    const int wid  = tid >> 5;
    const int wb   = wid & 1;                // b-half (64 rows)
    const int wk   = wid >> 1;               // k-group (64 k)
    const int bsub = lane & 7;               // rows wb*64 + bsub + 8i
    const int kq   = lane >> 3;              // 4 k-quarters
    const int kp0  = wk * 32 + kq * 8;       // first of 8 k-pairs (16 k)

    // ---- stage X rows [b0, b0+128) of channel c ----
#pragma unroll
    for (int s = 0; s < 8; s++) {
        int idx = s * 256 + tid;
        int row = idx >> 4, q = idx & 15;
        float4 v = ((const float4*)(X + ((size_t)(b0 + row) * NC + c) * ND))[q];
        *(float4*)(Xs + row * XPAD + q * 4) = v;
    }
    // ---- stage Y[c] transposed, k-pair-packed u64: Ys2[d][kp] ----
    const float* Yg = Yc + (size_t)c * NK * ND;
#pragma unroll
    for (int t = 0; t < 8; t++) {
        int idx = t * 256 + tid;             // 0..2047
        int kp = idx & 127, dc = idx >> 7;   // dc: 16 chunks of 4 d
        float4 a = *(const float4*)(Yg + (2 * kp)     * ND + dc * 4);
        float4 b = *(const float4*)(Yg + (2 * kp + 1) * ND + dc * 4);
        Ys2[(dc * 4 + 0) * YSTRIDE + kp] = f32x2_pack(a.x, b.x);
        Ys2[(dc * 4 + 1) * YSTRIDE + kp] = f32x2_pack(a.y, b.y);
        Ys2[(dc * 4 + 2) * YSTRIDE + kp] = f32x2_pack(a.z, b.z);
        Ys2[(dc * 4 + 3) * YSTRIDE + kp] = f32x2_pack(a.w, b.w);
    }
    __syncthreads();

    // ---- 8 b-rows x 16 k-cols per thread; acc = 8x8 packed f32x2 ----
    unsigned long long acc[8][8];
#pragma unroll
    for (int i = 0; i < 8; i++)
#pragma unroll
        for (int j = 0; j < 8; j++) acc[i][j] = 0ull;

    const float* xb = Xs + (wb * 64 + bsub) * XPAD;   // rows + 8i
    const unsigned long long* yb = Ys2 + kp0;

#pragma unroll 4
    for (int d = 0; d < ND; d += 2) {
        float2 xv[8];
#pragma unroll
        for (int i = 0; i < 8; i++)
            xv[i] = *(const float2*)(xb + i * 8 * XPAD + d);
        ulonglong2 y0[4], y1[4];
#pragma unroll
        for (int j = 0; j < 4; j++) {
            y0[j] = *(const ulonglong2*)(yb + (d)     * YSTRIDE + 2 * j);
            y1[j] = *(const ulonglong2*)(yb + (d + 1) * YSTRIDE + 2 * j);
        }
#pragma unroll
        for (int i = 0; i < 8; i++) {
            unsigned long long x0 = f32x2_dup(xv[i].x);
            unsigned long long x1 = f32x2_dup(xv[i].y);
#pragma unroll
            for (int j = 0; j < 4; j++) {
                f32x2_fma(acc[i][2 * j],     x0, y0[j].x);
                f32x2_fma(acc[i][2 * j + 1], x0, y0[j].y);
                f32x2_fma(acc[i][2 * j],     x1, y1[j].x);
                f32x2_fma(acc[i][2 * j + 1], x1, y1[j].y);
            }
        }
    }

    // ---- per-row max/argmax over this thread's 16 k + BN partial sums ----
    float s1 = 0.f, s2 = 0.f;
    float tmax[8]; int tidx[8];
#pragma unroll
    for (int i = 0; i < 8; i++) {
        tmax[i] = -3.4e38f; tidx[i] = 0;
#pragma unroll
        for (int j = 0; j < 8; j++) {
            float lo, hi;
            f32x2_unpack(acc[i][j], lo, hi);
            s1 += lo + hi;
            s2 = fmaf(lo, lo, s2);
            s2 = fmaf(hi, hi, s2);
            int klo = (kp0 + j) * 2;
            if (lo > tmax[i]) { tmax[i] = lo; tidx[i] = klo; }
            if (hi > tmax[i]) { tmax[i] = hi; tidx[i] = klo + 1; }
        }
    }

    // reduce across 4 k-quarters in warp (xor 8,16 keeps bsub fixed)
#pragma unroll
    for (int i = 0; i < 8; i++) {
#pragma unroll
        for (int off = 8; off <= 16; off <<= 1) {
            float v2 = __shfl_xor_sync(0xffffffffu, tmax[i], off);
            int   i2 = __shfl_xor_sync(0xffffffffu, tidx[i], off);
            if (v2 > tmax[i] || (v2 == tmax[i] && i2 < tidx[i])) {
                tmax[i] = v2; tidx[i] = i2;
            }
        }
    }
    if (kq == 0) {
#pragma unroll
        for (int i = 0; i < 8; i++) {
            int row = wb * 64 + bsub + i * 8;
            smax[wk * 128 + row] = tmax[i];
            sidx[wk * 128 + row] = tidx[i];
        }
    }

    // warp sum for BN stats
#pragma unroll
    for (int off = 16; off > 0; off >>= 1) {
        s1 += __shfl_xor_sync(0xffffffffu, s1, off);
        s2 += __shfl_xor_sync(0xffffffffu, s2, off);
    }
    if (lane == 0) { wsum[wid] = s1; wsq[wid] = s2; }
    __syncthreads();

    // cross-k-group max per row (ascending wk = ascending k => first-max kept)
    if (tid < 128) {
        const int row = tid;
        float m = smax[row]; int ki = sidx[row];
#pragma unroll
        for (int g = 1; g < 4; g++) {
            float v = smax[g * 128 + row]; int i2 = sidx[g * 128 + row];
            if (v > m || (v == m && i2 < ki)) { m = v; ki = i2; }
        }
        const size_t o = (size_t)(b0 + row) * NC + c;
        out[o] = (float)ki;
        out[(size_t)NB * NC + o] = m;
    }
    if (tid == 0) {
        float a = 0.f, b = 0.f;
#pragma unroll
        for (int w = 0; w < 8; w++) { a += wsum[w]; b += wsq[w]; }
        g_psum[c * GTILES + blockIdx.x]   = a;   // single writer, deterministic
        g_psumsq[c * GTILES + blockIdx.x] = b;
    }
}

__global__ void dpq_stats(const float* __restrict__ gamma,
                          const float* __restrict__ beta)
{
    const int c = threadIdx.x;          // 64 threads
    float s = 0.f, q = 0.f;
    for (int i = 0; i < GTILES; i++) {
        s += g_psum[c * GTILES + i];
        q += g_psumsq[c * GTILES + i];
    }
    const float inv = 1.0f / ((float)NB * (float)NK);
    const float mean = s * inv;
    const float var  = q * inv - mean * mean;   // biased, matches reference
    const float a = gamma[c] * rsqrtf(var + 1e-5f);
    g_affA[c] = a;
    g_affB[c] = fmaf(-mean, a, beta[c]);
}

__global__ void dpq_final(float* __restrict__ out)
{
    const int idx = blockIdx.x * blockDim.x + threadIdx.x;
    if (idx < NB * NC) {
        const int c = idx & (NC - 1);
        float* p = out + (size_t)NB * NC + idx;
        *p = fmaf(*p, g_affA[c], g_affB[c]);
    }
}

extern "C" void kernel_launch(void* const* d_in, const int* in_sizes, int n_in,
                              void* d_out, int out_size)
{
    const float* X     = (const float*)d_in[0];  // inputs (B,C,D)
    const float* Yc    = (const float*)d_in[1];  // centroids_k (C,K,D)
    const float* gamma = (const float*)d_in[2];
    const float* beta  = (const float*)d_in[3];
    float* out = (float*)d_out;

    const size_t smem = (size_t)64 * YSTRIDE * 8     // Ys2
                      + (size_t)128 * XPAD * 4       // Xs
                      + 512 * 4 + 512 * 4 + 16 * 4;  // reductions
    cudaFuncSetAttribute(dpq_main, cudaFuncAttributeMaxDynamicSharedMemorySize,
                         (int)smem);

    dim3 grid(GTILES, NC);
    dpq_main<<<grid, 256, smem>>>(X, Yc, out);
    dpq_stats<<<1, NC>>>(gamma, beta);
    dpq_final<<<(NB * NC + 255) / 256, 256>>>(out);

    if (out_size >= 2 * NB * NC + NC * NK * ND) {
        cudaMemcpyAsync(out + 2 * (size_t)NB * NC, Yc,
                        (size_t)NC * NK * ND * sizeof(float),
                        cudaMemcpyDeviceToDevice, 0);
    }
}